// round 8
// baseline (speedup 1.0000x reference)
#include <cuda_runtime.h>
#include <cuda_bf16.h>
#include <cstdint>

#define B_ 16
#define D_ 128
#define M_ 2048
#define N_ 4096
#define NT 32                 // 128-row tiles per batch
#define CHUNKS 128            // 32 row-tiles x 4 strips (circulant k-cover)
#define TILEB 16384           // 128 rows * 128 bytes (int8)

// Normalized rows scaled to int8 (q = round(127*zn)), [b][n][d] row-major
__device__ __align__(16) unsigned char g_zn[(size_t)B_ * N_ * D_];
// Per-row sum(2^d') and positive d' accumulators  (d' = 2*log2(e)*cos)
__device__ float g_rowsum[B_ * N_];
__device__ float g_rowpos[B_ * N_];

// ------------------------------------------------------- normalize + transpose
// Z[b][d][m] fp32 -> g_zn[b][n][d] int8; also zeroes scratch + out.
__global__ void normalize_kernel(const float* __restrict__ Zi,
                                 const float* __restrict__ Zj,
                                 float* __restrict__ out, int out_size) {
    __shared__ float tile[D_][33];
    __shared__ float part[8][32];
    __shared__ float rnorm_s[32];
    const int m0  = blockIdx.x * 32;
    const int src = blockIdx.y;
    const int b   = blockIdx.z;
    const float* Z = src ? Zj : Zi;
    const int tid = threadIdx.x;
    const int tx = tid & 31, ty = tid >> 5;

    // zero scratch slice (2048 blocks x 64 = 131072 floats) + out
    const int bid = blockIdx.x + 64 * (src + 2 * b);
    if (tid < 64) {
        int idx = bid * 64 + tid;
        if (idx < B_ * N_) g_rowsum[idx] = 0.f;
        else g_rowpos[idx - B_ * N_] = 0.f;
    }
    if (bid == 0) for (int i = tid; i < out_size; i += 256) out[i] = 0.f;

    const float* base = Z + (size_t)b * D_ * M_ + m0 + tx;
    float ss = 0.f;
#pragma unroll
    for (int d = ty; d < D_; d += 8) {
        float v = base[(size_t)d * M_];
        tile[d][tx] = v;
        ss += v * v;
    }
    part[ty][tx] = ss;
    __syncthreads();
    if (ty == 0) {
        float s = 0.f;
#pragma unroll
        for (int k = 0; k < 8; k++) s += part[k][tx];
        rnorm_s[tx] = 127.0f / fmaxf(sqrtf(s), 1e-8f);
    }
    __syncthreads();

    unsigned* out32 = reinterpret_cast<unsigned*>(g_zn);
    const size_t nbase = (size_t)b * N_ + (size_t)src * M_ + m0;
#pragma unroll
    for (int it = 0; it < 4; it++) {
        int idx = it * 256 + tid;
        int r = idx >> 5;
        int q = idx & 31;
        float rn = rnorm_s[r];
        int q0, q1, q2, q3;
        asm("cvt.rni.sat.s8.f32 %0, %1;" : "=r"(q0) : "f"(tile[4 * q][r] * rn));
        asm("cvt.rni.sat.s8.f32 %0, %1;" : "=r"(q1) : "f"(tile[4 * q + 1][r] * rn));
        asm("cvt.rni.sat.s8.f32 %0, %1;" : "=r"(q2) : "f"(tile[4 * q + 2][r] * rn));
        asm("cvt.rni.sat.s8.f32 %0, %1;" : "=r"(q3) : "f"(tile[4 * q + 3][r] * rn));
        unsigned pk = (q0 & 0xff) | ((q1 & 0xff) << 8)
                    | ((q2 & 0xff) << 16) | ((q3 & 0xff) << 24);
        out32[(nbase + r) * 32 + q] = pk;
    }
}

// ------------------------------------------------------------------- helpers
__device__ __forceinline__ unsigned swz_off(int row, int ch) {
    return (unsigned)(row * 128 + ((ch ^ (row & 7)) << 4));
}
__device__ __forceinline__ void ldsm_x4(unsigned addr, unsigned& r0, unsigned& r1,
                                        unsigned& r2, unsigned& r3) {
    asm volatile("ldmatrix.sync.aligned.m8n8.x4.shared.b16 {%0,%1,%2,%3}, [%4];"
                 : "=r"(r0), "=r"(r1), "=r"(r2), "=r"(r3) : "r"(addr));
}
__device__ __forceinline__ void mma_s8(int* c, const unsigned* a,
                                       unsigned b0, unsigned b1) {
    asm volatile("mma.sync.aligned.m16n8k32.row.col.s32.s8.s8.s32 "
                 "{%0,%1,%2,%3}, {%4,%5,%6,%7}, {%8,%9}, {%0,%1,%2,%3};"
                 : "+r"(c[0]), "+r"(c[1]), "+r"(c[2]), "+r"(c[3])
                 : "r"(a[0]), "r"(a[1]), "r"(a[2]), "r"(a[3]), "r"(b0), "r"(b1));
}
__device__ __forceinline__ float ex2f(float x) {
    float y; asm("ex2.approx.f32 %0, %1;" : "=f"(y) : "f"(x)); return y;
}
__device__ __forceinline__ float lg2f(float x) {
    float y; asm("lg2.approx.f32 %0, %1;" : "=f"(y) : "f"(x)); return y;
}
__device__ __forceinline__ void cp16(unsigned dst, const void* src) {
    asm volatile("cp.async.cg.shared.global [%0], [%1], 16;"
                 :: "r"(dst), "l"(src) : "memory");
}
#define CP_COMMIT() asm volatile("cp.async.commit_group;" ::: "memory")

__device__ __forceinline__ void load_tile(unsigned sdst, const char* gsrc, int tid) {
#pragma unroll
    for (int it = 0; it < 2; it++) {
        int idx = it * 512 + tid;          // 1024 x 16B chunks, 512 threads
        int row = idx >> 3, ch = idx & 7;
        cp16(sdst + swz_off(row, ch), gsrc + row * 128 + ch * 16);
    }
}

// 32x32 per-warp MMA for one 128x128 tile (16 warps)
__device__ __forceinline__ void kloop(int acc[2][4][4], unsigned sA, unsigned sBt,
                                      int rowA, int colB, int lane) {
#pragma unroll
    for (int mi = 0; mi < 2; mi++)
#pragma unroll
        for (int ng = 0; ng < 4; ng++)
#pragma unroll
            for (int q = 0; q < 4; q++) acc[mi][ng][q] = 0;
#pragma unroll
    for (int k = 0; k < 4; k++) {
        unsigned a[2][4], bb[2][4];
        const int ch = 2 * k + (lane >> 4);
        const int rl = lane & 15;
#pragma unroll
        for (int mi = 0; mi < 2; mi++)
            ldsm_x4(sA + swz_off(rowA + mi * 16 + rl, ch),
                    a[mi][0], a[mi][1], a[mi][2], a[mi][3]);
#pragma unroll
        for (int g = 0; g < 2; g++)
            ldsm_x4(sBt + swz_off(colB + g * 16 + rl, ch),
                    bb[g][0], bb[g][1], bb[g][2], bb[g][3]);
#pragma unroll
        for (int mi = 0; mi < 2; mi++)
#pragma unroll
            for (int ng = 0; ng < 4; ng++)
                mma_s8(acc[mi][ng], a[mi],
                       bb[ng >> 1][ng & 1], bb[ng >> 1][(ng & 1) + 2]);
    }
}

// Epilogue (transform + row partials + csum write). Caller barriers + push.
__device__ __forceinline__ void epilogue(int acc[2][4][4], int kk, int j,
                                         int rowA, int colB, int lane, int w,
                                         float rs[4], float* rowpos_b,
                                         float* apos, float (*csum)[128]) {
    const float K = 2.885390081777927f / 16129.0f;  // 2*log2(e)/127^2
    const bool dt = (kk == 0);
    const bool pt = (kk == 16);
    if (!dt && !pt) {
#pragma unroll
        for (int mi = 0; mi < 2; mi++)
#pragma unroll
            for (int ng = 0; ng < 4; ng++)
#pragma unroll
                for (int q = 0; q < 4; q++) {
                    float e = ex2f((float)acc[mi][ng][q] * K);
                    acc[mi][ng][q] = __float_as_int(e);
                    rs[mi * 2 + (q >> 1)] += e;
                }
    } else {
#pragma unroll
        for (int mi = 0; mi < 2; mi++)
#pragma unroll
            for (int ng = 0; ng < 4; ng++)
#pragma unroll
                for (int q = 0; q < 4; q++) {
                    const int lr = rowA + mi * 16 + (q >> 1) * 8 + (lane >> 2);
                    const int lc = colB + ng * 8 + ((lane & 3) << 1) + (q & 1);
                    const float dv = (float)acc[mi][ng][q] * K;
                    if (pt && lr == lc) {
                        atomicAdd(&apos[lr], dv);
                        atomicAdd(&rowpos_b[j * 128 + lr], dv);
                    }
                    float e = (dt && lr == lc) ? 0.f : ex2f(dv);
                    acc[mi][ng][q] = __float_as_int(e);
                    rs[mi * 2 + (q >> 1)] += e;
                }
    }
    // column partials -> csum
#pragma unroll
    for (int ng = 0; ng < 4; ng++)
#pragma unroll
        for (int ql = 0; ql < 2; ql++) {
            float cs = __int_as_float(acc[0][ng][ql])
                     + __int_as_float(acc[0][ng][ql + 2])
                     + __int_as_float(acc[1][ng][ql])
                     + __int_as_float(acc[1][ng][ql + 2]);
            cs += __shfl_xor_sync(0xffffffffu, cs, 4);
            cs += __shfl_xor_sync(0xffffffffu, cs, 8);
            cs += __shfl_xor_sync(0xffffffffu, cs, 16);
            if (lane < 4)
                csum[w >> 2][colB + ng * 8 + lane * 2 + ql] = cs;
        }
}

// ------------------------------------------------------------------ main pass
// Circulant cover; 512 threads = 16 warps of 32x32. Two-tile in-warp skew:
// issue MMA(t) into acc[t&1], then run epilogue(t-1) from acc[(t-1)&1]
// while the tensor pipe drains MMA(t).
__global__ __launch_bounds__(512, 1) void simclr_chunk_kernel() {
    extern __shared__ char smem[];          // A 16K | B0 | B1 | B2
    __shared__ float csum[4][128];
    __shared__ float asum[128], apos[128];

    const int b = blockIdx.y;
    const int ti = blockIdx.x >> 2;
    const int s  = blockIdx.x & 3;
    const int k0 = s * 4;
    const bool has16 = (s == 3 && ti < 16);
    const int nt = has16 ? 5 : 4;

    const int tid = threadIdx.x;
    const int lane = tid & 31, w = tid >> 5;
    const int rowA = (w >> 2) * 32;
    const int colB = (w & 3) * 32;

    unsigned sA = (unsigned)__cvta_generic_to_shared(smem);
    unsigned sB[3] = {sA + 16384, sA + 32768, sA + 49152};

    if (tid < 128) { asum[tid] = 0.f; apos[tid] = 0.f; }

    const char* zb = (const char*)(g_zn + (size_t)b * N_ * D_);
    load_tile(sA, zb + (size_t)ti * TILEB, tid);
    load_tile(sB[0], zb + (size_t)(((ti + k0) & 31)) * TILEB, tid);
    CP_COMMIT();
    load_tile(sB[1], zb + (size_t)(((ti + k0 + 1) & 31)) * TILEB, tid);
    CP_COMMIT();
    load_tile(sB[2], zb + (size_t)(((ti + k0 + 2) & 31)) * TILEB, tid);
    CP_COMMIT();

    float rs[4] = {0.f, 0.f, 0.f, 0.f};
    float* rowsum_b = g_rowsum + b * N_;
    float* rowpos_b = g_rowpos + b * N_;
    int accA[2][4][4], accB[2][4][4];

    int bufi = 0;
    for (int t = 0; t < nt; t++) {
        asm volatile("cp.async.wait_group 2;" ::: "memory");
        __syncthreads();   // also: prior csum push read done before next write

        // MMA tile t (async-ish: results not read this iteration)
        if (t & 1) kloop(accB, sA, sB[bufi], rowA, colB, lane);
        else       kloop(accA, sA, sB[bufi], rowA, colB, lane);

        // epilogue tile t-1 (MUFU/I2F overlap tensor drain of tile t)
        if (t > 0) {
            const int kkp = k0 + t - 1;
            const int jp = (ti + kkp) & 31;
            if (t & 1) epilogue(accA, kkp, jp, rowA, colB, lane, w,
                                rs, rowpos_b, apos, csum);
            else       epilogue(accB, kkp, jp, rowA, colB, lane, w,
                                rs, rowpos_b, apos, csum);
        }
        __syncthreads();   // ldsm(t) done -> safe to overwrite buffer; csum ready

        if (t + 3 < nt)
            load_tile(sB[bufi], zb + (size_t)(((ti + k0 + t + 3) & 31)) * TILEB, tid);
        CP_COMMIT();

        // push column sums of tile t-1 (skip diagonal tile kk==0)
        if (t > 0) {
            const int kkp = k0 + t - 1;
            if (kkp != 0 && tid < 128) {
                const int jp = (ti + kkp) & 31;
                float cs = (csum[0][tid] + csum[1][tid])
                         + (csum[2][tid] + csum[3][tid]);
                atomicAdd(&rowsum_b[jp * 128 + tid], cs);
            }
        }
        bufi = (bufi == 2) ? 0 : bufi + 1;
    }

    // final tile epilogue + push
    {
        const int tl = nt - 1;
        const int kk = k0 + tl;
        const int j = (ti + kk) & 31;
        __syncthreads();   // prior push reads done before csum rewrite
        if (tl & 1) epilogue(accB, kk, j, rowA, colB, lane, w,
                             rs, rowpos_b, apos, csum);
        else        epilogue(accA, kk, j, rowA, colB, lane, w,
                             rs, rowpos_b, apos, csum);
        __syncthreads();
        if (kk != 0 && tid < 128) {
            float cs = (csum[0][tid] + csum[1][tid])
                     + (csum[2][tid] + csum[3][tid]);
            atomicAdd(&rowsum_b[j * 128 + tid], cs);
        }
    }

    // CTA-end: quad-reduce row partials, combine, push rows of tile ti
#pragma unroll
    for (int idx = 0; idx < 4; idx++) {
        rs[idx] += __shfl_xor_sync(0xffffffffu, rs[idx], 1);
        rs[idx] += __shfl_xor_sync(0xffffffffu, rs[idx], 2);
    }
    if ((lane & 3) == 0) {
#pragma unroll
        for (int idx = 0; idx < 4; idx++)
            atomicAdd(&asum[rowA + (idx >> 1) * 16 + (idx & 1) * 8 + (lane >> 2)],
                      rs[idx]);
    }
    __syncthreads();
    if (tid < 128) {
        atomicAdd(&rowsum_b[ti * 128 + tid], asum[tid]);
        if (has16) atomicAdd(&rowpos_b[ti * 128 + tid], apos[tid]);
    }
}

// -------------------------------------------------------------------- finalize
__global__ void finalize_kernel(float* __restrict__ out) {
    const int r = blockIdx.x * 1024 + threadIdx.x;
    float v = 0.6931471805599453f * (lg2f(g_rowsum[r]) - g_rowpos[r]);
#pragma unroll
    for (int o = 16; o > 0; o >>= 1) v += __shfl_xor_sync(0xffffffffu, v, o);
    __shared__ float red[32];
    const int w = threadIdx.x >> 5;
    if ((threadIdx.x & 31) == 0) red[w] = v;
    __syncthreads();
    if (threadIdx.x < 32) {
        float s = red[threadIdx.x];
#pragma unroll
        for (int o = 16; o > 0; o >>= 1) s += __shfl_xor_sync(0xffffffffu, s, o);
        if (threadIdx.x == 0)
            atomicAdd(out, s * (1.f / ((float)B_ * (float)N_)));
    }
}

// ----------------------------------------------------------------- entry point
extern "C" void kernel_launch(void* const* d_in, const int* in_sizes, int n_in,
                              void* d_out, int out_size) {
    const float* Zi = (const float*)d_in[0];
    const float* Zj = (const float*)d_in[1];
    float* out = (float*)d_out;
    (void)in_sizes; (void)n_in;

    cudaFuncSetAttribute(simclr_chunk_kernel,
                         cudaFuncAttributeMaxDynamicSharedMemorySize, 65536);

    normalize_kernel<<<dim3(M_ / 32, 2, B_), 256>>>(Zi, Zj, out, out_size);
    simclr_chunk_kernel<<<dim3(CHUNKS, B_), 512, 65536>>>();
    finalize_kernel<<<B_ * N_ / 1024, 1024>>>(out);
}

// round 9
// speedup vs baseline: 1.1305x; 1.1305x over previous
#include <cuda_runtime.h>
#include <cuda_bf16.h>
#include <cstdint>

#define B_ 16
#define D_ 128
#define M_ 2048
#define N_ 4096
#define NT 32                 // 128-row tiles per batch
#define CHUNKS 128            // 32 row-tiles x 4 strips (circulant k-cover)
#define TILEB 16384           // 128 rows * 128 bytes (int8)

// Normalized rows scaled to int8 (q = round(127*zn)), [b][n][d] row-major
__device__ __align__(16) unsigned char g_zn[(size_t)B_ * N_ * D_];
// Per-row sum(2^d') and positive d' accumulators  (d' = 2*log2(e)*cos)
__device__ float g_rowsum[B_ * N_];
__device__ float g_rowpos[B_ * N_];

// ------------------------------------------------------- normalize + transpose
// Z[b][d][m] fp32 -> g_zn[b][n][d] int8 = round(127*z/max(||z||,1e-8)).
// XOR smem layout: conflict-free in both phases. Also zeroes scratch + out.
__global__ void normalize_kernel(const float* __restrict__ Zi,
                                 const float* __restrict__ Zj,
                                 float* __restrict__ out, int out_size) {
    __shared__ float tile[32 * 128];     // [m-lane][d ^ m]
    __shared__ float part[8][32];
    __shared__ float rnorm_s[32];
    const int m0  = blockIdx.x * 32;
    const int src = blockIdx.y;
    const int b   = blockIdx.z;
    const float* Z = src ? Zj : Zi;
    const int tid = threadIdx.x;
    const int tx = tid & 31, ty = tid >> 5;

    // zero scratch slice (2048 blocks x 64 = 131072 floats) + out
    const int bid = blockIdx.x + 64 * (src + 2 * b);
    if (tid < 64) {
        int idx = bid * 64 + tid;
        if (idx < B_ * N_) g_rowsum[idx] = 0.f;
        else g_rowpos[idx - B_ * N_] = 0.f;
    }
    if (bid == 0) for (int i = tid; i < out_size; i += 256) out[i] = 0.f;

    const float* base = Z + (size_t)b * D_ * M_ + m0 + tx;
    float ss = 0.f;
#pragma unroll
    for (int d = ty; d < D_; d += 8) {
        float v = base[(size_t)d * M_];
        tile[tx * 128 + (d ^ tx)] = v;    // lane=tx, bank=(d^tx): conflict-free
        ss += v * v;
    }
    part[ty][tx] = ss;
    __syncthreads();
    if (ty == 0) {
        float s = 0.f;
#pragma unroll
        for (int k = 0; k < 8; k++) s += part[k][tx];
        rnorm_s[tx] = 127.0f / fmaxf(sqrtf(s), 1e-8f);
    }
    __syncthreads();

    // quantize: lane q covers d = q + 32i; warp-group rg covers 4 rows
    const int q  = tid & 31;
    const int rg = tid >> 5;
    unsigned char* outb = g_zn
        + ((size_t)b * N_ + (size_t)src * M_ + m0) * 128;
#pragma unroll
    for (int it = 0; it < 4; it++) {
        const int r = rg * 4 + it;
        const float rn = rnorm_s[r];
#pragma unroll
        for (int i = 0; i < 4; i++) {
            const int d = q + 32 * i;
            float v = tile[r * 128 + (d ^ r)] * rn;  // bank=(q^r): conflict-free
            int qv;
            asm("cvt.rni.sat.s8.f32 %0, %1;" : "=r"(qv) : "f"(v));
            outb[(size_t)r * 128 + d] = (unsigned char)qv;
        }
    }
}

// ------------------------------------------------------------------- helpers
__device__ __forceinline__ unsigned swz_off(int row, int ch) {
    return (unsigned)(row * 128 + ((ch ^ (row & 7)) << 4));
}
__device__ __forceinline__ void ldsm_x4(unsigned addr, unsigned& r0, unsigned& r1,
                                        unsigned& r2, unsigned& r3) {
    asm volatile("ldmatrix.sync.aligned.m8n8.x4.shared.b16 {%0,%1,%2,%3}, [%4];"
                 : "=r"(r0), "=r"(r1), "=r"(r2), "=r"(r3) : "r"(addr));
}
__device__ __forceinline__ void mma_s8(int* c, const unsigned* a,
                                       unsigned b0, unsigned b1) {
    asm volatile("mma.sync.aligned.m16n8k32.row.col.s32.s8.s8.s32 "
                 "{%0,%1,%2,%3}, {%4,%5,%6,%7}, {%8,%9}, {%0,%1,%2,%3};"
                 : "+r"(c[0]), "+r"(c[1]), "+r"(c[2]), "+r"(c[3])
                 : "r"(a[0]), "r"(a[1]), "r"(a[2]), "r"(a[3]), "r"(b0), "r"(b1));
}
__device__ __forceinline__ float ex2f(float x) {
    float y; asm("ex2.approx.f32 %0, %1;" : "=f"(y) : "f"(x)); return y;
}
__device__ __forceinline__ float lg2f(float x) {
    float y; asm("lg2.approx.f32 %0, %1;" : "=f"(y) : "f"(x)); return y;
}
__device__ __forceinline__ void cp16(unsigned dst, const void* src) {
    asm volatile("cp.async.cg.shared.global [%0], [%1], 16;"
                 :: "r"(dst), "l"(src) : "memory");
}
#define CP_COMMIT() asm volatile("cp.async.commit_group;" ::: "memory")

__device__ __forceinline__ void load_tile(unsigned sdst, const char* gsrc, int tid) {
#pragma unroll
    for (int it = 0; it < 4; it++) {
        int idx = it * 256 + tid;          // 1024 x 16B chunks
        int row = idx >> 3, ch = idx & 7;
        cp16(sdst + swz_off(row, ch), gsrc + row * 128 + ch * 16);
    }
}

// magic int->float: exact for |i| < 2^22
#define MAGIC_F 12582912.0f
#define MAGIC_I 0x4B400000

// ------------------------------------------------------------------ main pass
// Circulant pair cover (R7 structure): CTA = (row-tile i, strip s); strip s
// covers k=4s..4s+3 (+k=16 on s=3 for i<16); j=(i+k)&31. 256 threads, occ 2.
__global__ __launch_bounds__(256, 2) void simclr_chunk_kernel() {
    extern __shared__ char smem[];          // A 16K | B0 | B1 | B2 (16K each)
    __shared__ float csum[4][128];
    __shared__ float asum[128], apos[128];

    const int b = blockIdx.y;
    const int ti = blockIdx.x >> 2;
    const int s  = blockIdx.x & 3;
    const int k0 = s * 4;
    const bool has16 = (s == 3 && ti < 16);
    const int nt = has16 ? 5 : 4;

    const int tid = threadIdx.x;
    const int lane = tid & 31, w = tid >> 5;
    const int rowA = (w >> 1) * 32;
    const int colB = (w & 1) * 64;

    unsigned sA = (unsigned)__cvta_generic_to_shared(smem);
    unsigned sB[3] = {sA + 16384, sA + 32768, sA + 49152};

    if (tid < 128) { asum[tid] = 0.f; apos[tid] = 0.f; }

    const char* zb = (const char*)(g_zn + (size_t)b * N_ * D_);
    load_tile(sA, zb + (size_t)ti * TILEB, tid);
    load_tile(sB[0], zb + (size_t)(((ti + k0) & 31)) * TILEB, tid);
    CP_COMMIT();
    load_tile(sB[1], zb + (size_t)(((ti + k0 + 1) & 31)) * TILEB, tid);
    CP_COMMIT();
    load_tile(sB[2], zb + (size_t)(((ti + k0 + 2) & 31)) * TILEB, tid);
    CP_COMMIT();

    float rs[4] = {0.f, 0.f, 0.f, 0.f};
    float* rowsum_b = g_rowsum + b * N_;
    float* rowpos_b = g_rowpos + b * N_;
    const float K  = 2.885390081777927f / 16129.0f;  // 2*log2(e) / 127^2
    const float C0 = -MAGIC_F * K;

    int bufi = 0;
    for (int t = 0; t < nt; t++) {
        asm volatile("cp.async.wait_group 2;" ::: "memory");
        __syncthreads();

        const int kk = k0 + t;
        const int j = (ti + kk) & 31;
        const unsigned sBt = sB[bufi];
        const bool dt = (kk == 0);
        const bool pt = (kk == 16);

        int acc[2][8][4];
#pragma unroll
        for (int mi = 0; mi < 2; mi++)
#pragma unroll
            for (int ng = 0; ng < 8; ng++)
#pragma unroll
                for (int q = 0; q < 4; q++) acc[mi][ng][q] = 0;

#pragma unroll
        for (int k = 0; k < 4; k++) {            // k32 per step
            unsigned a[2][4], bb[4][4];
            const int ch = 2 * k + (lane >> 4);
            const int rl = lane & 15;
#pragma unroll
            for (int mi = 0; mi < 2; mi++)
                ldsm_x4(sA + swz_off(rowA + mi * 16 + rl, ch),
                        a[mi][0], a[mi][1], a[mi][2], a[mi][3]);
#pragma unroll
            for (int g = 0; g < 4; g++)
                ldsm_x4(sBt + swz_off(colB + g * 16 + rl, ch),
                        bb[g][0], bb[g][1], bb[g][2], bb[g][3]);
#pragma unroll
            for (int mi = 0; mi < 2; mi++)
#pragma unroll
                for (int ng = 0; ng < 8; ng++)
                    mma_s8(acc[mi][ng], a[mi],
                           bb[ng >> 1][ng & 1], bb[ng >> 1][(ng & 1) + 2]);
        }

        // transform in place: exp2(K*acc) via magic int->float (no I2F)
        if (!dt && !pt) {
#pragma unroll
            for (int mi = 0; mi < 2; mi++)
#pragma unroll
                for (int ng = 0; ng < 8; ng++)
#pragma unroll
                    for (int q = 0; q < 4; q++) {
                        float f = __int_as_float(acc[mi][ng][q] + MAGIC_I);
                        acc[mi][ng][q] = __float_as_int(ex2f(fmaf(f, K, C0)));
                    }
        } else {
#pragma unroll
            for (int mi = 0; mi < 2; mi++)
#pragma unroll
                for (int ng = 0; ng < 8; ng++)
#pragma unroll
                    for (int q = 0; q < 4; q++) {
                        const int lr = rowA + mi * 16 + (q >> 1) * 8 + (lane >> 2);
                        const int lc = colB + ng * 8 + ((lane & 3) << 1) + (q & 1);
                        float f = __int_as_float(acc[mi][ng][q] + MAGIC_I);
                        const float dv = fmaf(f, K, C0);
                        if (pt && lr == lc) {
                            atomicAdd(&apos[lr], dv);
                            atomicAdd(&rowpos_b[j * 128 + lr], dv);
                        }
                        acc[mi][ng][q] = __float_as_int(
                            (dt && lr == lc) ? 0.f : ex2f(dv));
                    }
        }

        // row partials (registers, reduced at CTA end)
#pragma unroll
        for (int idx = 0; idx < 4; idx++) {
            const int mi = idx >> 1, qh = idx & 1;
            float r = 0.f;
#pragma unroll
            for (int ng = 0; ng < 8; ng++)
                r += __int_as_float(acc[mi][ng][2 * qh])
                   + __int_as_float(acc[mi][ng][2 * qh + 1]);
            rs[idx] += r;
        }

        // column partials -> csum (conflict-free slots)
#pragma unroll
        for (int ng = 0; ng < 8; ng++)
#pragma unroll
            for (int ql = 0; ql < 2; ql++) {
                float cs = __int_as_float(acc[0][ng][ql])
                         + __int_as_float(acc[0][ng][ql + 2])
                         + __int_as_float(acc[1][ng][ql])
                         + __int_as_float(acc[1][ng][ql + 2]);
                cs += __shfl_xor_sync(0xffffffffu, cs, 4);
                cs += __shfl_xor_sync(0xffffffffu, cs, 8);
                cs += __shfl_xor_sync(0xffffffffu, cs, 16);
                if (lane < 4)
                    csum[w >> 1][colB + ng * 8 + lane * 2 + ql] = cs;
            }
        __syncthreads();

        // prefetch B_{t+3} into the buffer just consumed
        if (t + 3 < nt)
            load_tile(sB[bufi], zb + (size_t)(((ti + k0 + t + 3) & 31)) * TILEB, tid);
        CP_COMMIT();

        // push column sums to rows of tile j (skip diagonal tile)
        if (!dt && tid < 128) {
            float cs = (csum[0][tid] + csum[1][tid])
                     + (csum[2][tid] + csum[3][tid]);
            atomicAdd(&rowsum_b[j * 128 + tid], cs);
        }
        bufi = (bufi == 2) ? 0 : bufi + 1;
    }

    // CTA-end: quad-reduce row partials, combine, push rows of tile ti
#pragma unroll
    for (int idx = 0; idx < 4; idx++) {
        rs[idx] += __shfl_xor_sync(0xffffffffu, rs[idx], 1);
        rs[idx] += __shfl_xor_sync(0xffffffffu, rs[idx], 2);
    }
    if ((lane & 3) == 0) {
#pragma unroll
        for (int idx = 0; idx < 4; idx++)
            atomicAdd(&asum[rowA + (idx >> 1) * 16 + (idx & 1) * 8 + (lane >> 2)],
                      rs[idx]);
    }
    __syncthreads();
    if (tid < 128) {
        atomicAdd(&rowsum_b[ti * 128 + tid], asum[tid]);
        if (has16) atomicAdd(&rowpos_b[ti * 128 + tid], apos[tid]);
    }
}

// -------------------------------------------------------------------- finalize
__global__ void finalize_kernel(float* __restrict__ out) {
    const int r = blockIdx.x * 1024 + threadIdx.x;
    float v = 0.6931471805599453f * (lg2f(g_rowsum[r]) - g_rowpos[r]);
#pragma unroll
    for (int o = 16; o > 0; o >>= 1) v += __shfl_xor_sync(0xffffffffu, v, o);
    __shared__ float red[32];
    const int w = threadIdx.x >> 5;
    if ((threadIdx.x & 31) == 0) red[w] = v;
    __syncthreads();
    if (threadIdx.x < 32) {
        float s = red[threadIdx.x];
#pragma unroll
        for (int o = 16; o > 0; o >>= 1) s += __shfl_xor_sync(0xffffffffu, s, o);
        if (threadIdx.x == 0)
            atomicAdd(out, s * (1.f / ((float)B_ * (float)N_)));
    }
}

// ----------------------------------------------------------------- entry point
extern "C" void kernel_launch(void* const* d_in, const int* in_sizes, int n_in,
                              void* d_out, int out_size) {
    const float* Zi = (const float*)d_in[0];
    const float* Zj = (const float*)d_in[1];
    float* out = (float*)d_out;
    (void)in_sizes; (void)n_in;

    cudaFuncSetAttribute(simclr_chunk_kernel,
                         cudaFuncAttributeMaxDynamicSharedMemorySize, 65536);

    normalize_kernel<<<dim3(M_ / 32, 2, B_), 256>>>(Zi, Zj, out, out_size);
    simclr_chunk_kernel<<<dim3(CHUNKS, B_), 256, 65536>>>();
    finalize_kernel<<<B_ * N_ / 1024, 1024>>>(out);
}

// round 10
// speedup vs baseline: 1.2910x; 1.1419x over previous
#include <cuda_runtime.h>
#include <cuda_bf16.h>
#include <cuda_fp16.h>
#include <cstdint>

#define B_ 16
#define D_ 128
#define M_ 2048
#define N_ 4096
#define NT 32                 // 128-row tiles per batch
#define CHUNKS 128            // 32 row-tiles x 4 strips (circulant k-cover)
#define TILEB 16384           // 128 rows * 128 bytes (int8)

// Normalized rows scaled to int8 (q = round(127*zn)), [b][n][d] row-major
__device__ __align__(16) unsigned char g_zn[(size_t)B_ * N_ * D_];
// Per-row sum(2^d') and positive d' accumulators  (d' = 2*log2(e)*cos)
__device__ float g_rowsum[B_ * N_];
__device__ float g_rowpos[B_ * N_];

// ------------------------------------------------------- normalize + transpose
__global__ void normalize_kernel(const float* __restrict__ Zi,
                                 const float* __restrict__ Zj,
                                 float* __restrict__ out, int out_size) {
    __shared__ float tile[32 * 128];     // [m-lane][d ^ m]
    __shared__ float part[8][32];
    __shared__ float rnorm_s[32];
    const int m0  = blockIdx.x * 32;
    const int src = blockIdx.y;
    const int b   = blockIdx.z;
    const float* Z = src ? Zj : Zi;
    const int tid = threadIdx.x;
    const int tx = tid & 31, ty = tid >> 5;

    const int bid = blockIdx.x + 64 * (src + 2 * b);
    if (tid < 64) {
        int idx = bid * 64 + tid;
        if (idx < B_ * N_) g_rowsum[idx] = 0.f;
        else g_rowpos[idx - B_ * N_] = 0.f;
    }
    if (bid == 0) for (int i = tid; i < out_size; i += 256) out[i] = 0.f;

    const float* base = Z + (size_t)b * D_ * M_ + m0 + tx;
    float ss = 0.f;
#pragma unroll
    for (int d = ty; d < D_; d += 8) {
        float v = base[(size_t)d * M_];
        tile[tx * 128 + (d ^ tx)] = v;
        ss += v * v;
    }
    part[ty][tx] = ss;
    __syncthreads();
    if (ty == 0) {
        float s = 0.f;
#pragma unroll
        for (int k = 0; k < 8; k++) s += part[k][tx];
        rnorm_s[tx] = 127.0f / fmaxf(sqrtf(s), 1e-8f);
    }
    __syncthreads();

    const int q  = tid & 31;
    const int rg = tid >> 5;
    unsigned char* outb = g_zn
        + ((size_t)b * N_ + (size_t)src * M_ + m0) * 128;
#pragma unroll
    for (int it = 0; it < 4; it++) {
        const int r = rg * 4 + it;
        const float rn = rnorm_s[r];
#pragma unroll
        for (int i = 0; i < 4; i++) {
            const int d = q + 32 * i;
            float v = tile[r * 128 + (d ^ r)] * rn;
            int qv;
            asm("cvt.rni.sat.s8.f32 %0, %1;" : "=r"(qv) : "f"(v));
            outb[(size_t)r * 128 + d] = (unsigned char)qv;
        }
    }
}

// ------------------------------------------------------------------- helpers
__device__ __forceinline__ unsigned swz_off(int row, int ch) {
    return (unsigned)(row * 128 + ((ch ^ (row & 7)) << 4));
}
__device__ __forceinline__ void ldsm_x4(unsigned addr, unsigned& r0, unsigned& r1,
                                        unsigned& r2, unsigned& r3) {
    asm volatile("ldmatrix.sync.aligned.m8n8.x4.shared.b16 {%0,%1,%2,%3}, [%4];"
                 : "=r"(r0), "=r"(r1), "=r"(r2), "=r"(r3) : "r"(addr));
}
__device__ __forceinline__ void mma_s8(int* c, const unsigned* a,
                                       unsigned b0, unsigned b1) {
    asm volatile("mma.sync.aligned.m16n8k32.row.col.s32.s8.s8.s32 "
                 "{%0,%1,%2,%3}, {%4,%5,%6,%7}, {%8,%9}, {%0,%1,%2,%3};"
                 : "+r"(c[0]), "+r"(c[1]), "+r"(c[2]), "+r"(c[3])
                 : "r"(a[0]), "r"(a[1]), "r"(a[2]), "r"(a[3]), "r"(b0), "r"(b1));
}
__device__ __forceinline__ float ex2f(float x) {
    float y; asm("ex2.approx.f32 %0, %1;" : "=f"(y) : "f"(x)); return y;
}
__device__ __forceinline__ float lg2f(float x) {
    float y; asm("lg2.approx.f32 %0, %1;" : "=f"(y) : "f"(x)); return y;
}
__device__ __forceinline__ unsigned pack_h2(float hi, float lo) {
    unsigned p;
    asm("cvt.rn.f16x2.f32 %0, %1, %2;" : "=r"(p) : "f"(hi), "f"(lo));
    return p;
}
__device__ __forceinline__ unsigned ex2_h2(unsigned x) {
    unsigned y; asm("ex2.approx.f16x2 %0, %1;" : "=r"(y) : "r"(x)); return y;
}
__device__ __forceinline__ unsigned hadd2u(unsigned a, unsigned b) {
    unsigned c; asm("add.rn.f16x2 %0, %1, %2;" : "=r"(c) : "r"(a), "r"(b));
    return c;
}
__device__ __forceinline__ float2 h2_to_f2(unsigned u) {
    __half2 h = *reinterpret_cast<__half2*>(&u);
    return __half22float2(h);
}
__device__ __forceinline__ void cp16(unsigned dst, const void* src) {
    asm volatile("cp.async.cg.shared.global [%0], [%1], 16;"
                 :: "r"(dst), "l"(src) : "memory");
}
#define CP_COMMIT() asm volatile("cp.async.commit_group;" ::: "memory")

__device__ __forceinline__ void load_tile(unsigned sdst, const char* gsrc, int tid) {
#pragma unroll
    for (int it = 0; it < 4; it++) {
        int idx = it * 256 + tid;
        int row = idx >> 3, ch = idx & 7;
        cp16(sdst + swz_off(row, ch), gsrc + row * 128 + ch * 16);
    }
}

#define MAGIC_F 12582912.0f
#define MAGIC_I 0x4B400000

// ------------------------------------------------------------------ main pass
__global__ __launch_bounds__(256, 2) void simclr_chunk_kernel() {
    extern __shared__ char smem[];          // A 16K | B0 | B1 | B2 (16K each)
    __shared__ float csum[4][128];
    __shared__ float asum[128], apos[128];

    const int b = blockIdx.y;
    const int ti = blockIdx.x >> 2;
    const int s  = blockIdx.x & 3;
    const int k0 = s * 4;
    const bool has16 = (s == 3 && ti < 16);
    const int nt = has16 ? 5 : 4;

    const int tid = threadIdx.x;
    const int lane = tid & 31, w = tid >> 5;
    const int rowA = (w >> 1) * 32;
    const int colB = (w & 1) * 64;

    unsigned sA = (unsigned)__cvta_generic_to_shared(smem);
    unsigned sB[3] = {sA + 16384, sA + 32768, sA + 49152};

    if (tid < 128) { asum[tid] = 0.f; apos[tid] = 0.f; }

    const char* zb = (const char*)(g_zn + (size_t)b * N_ * D_);
    load_tile(sA, zb + (size_t)ti * TILEB, tid);
    load_tile(sB[0], zb + (size_t)(((ti + k0) & 31)) * TILEB, tid);
    CP_COMMIT();
    load_tile(sB[1], zb + (size_t)(((ti + k0 + 1) & 31)) * TILEB, tid);
    CP_COMMIT();
    load_tile(sB[2], zb + (size_t)(((ti + k0 + 2) & 31)) * TILEB, tid);
    CP_COMMIT();

    float rs[4] = {0.f, 0.f, 0.f, 0.f};
    float* rowsum_b = g_rowsum + b * N_;
    float* rowpos_b = g_rowpos + b * N_;
    const float K  = 2.885390081777927f / 16129.0f;  // 2*log2(e) / 127^2
    const float C0 = -MAGIC_F * K;

    int bufi = 0;
    for (int t = 0; t < nt; t++) {
        asm volatile("cp.async.wait_group 2;" ::: "memory");
        __syncthreads();

        const int kk = k0 + t;
        const int j = (ti + kk) & 31;
        const unsigned sBt = sB[bufi];
        const bool dt = (kk == 0);
        const bool pt = (kk == 16);

        int acc[2][8][4];
#pragma unroll
        for (int mi = 0; mi < 2; mi++)
#pragma unroll
            for (int ng = 0; ng < 8; ng++)
#pragma unroll
                for (int q = 0; q < 4; q++) acc[mi][ng][q] = 0;

#pragma unroll
        for (int k = 0; k < 4; k++) {            // k32 per step
            unsigned a[2][4], bb[4][4];
            const int ch = 2 * k + (lane >> 4);
            const int rl = lane & 15;
#pragma unroll
            for (int mi = 0; mi < 2; mi++)
                ldsm_x4(sA + swz_off(rowA + mi * 16 + rl, ch),
                        a[mi][0], a[mi][1], a[mi][2], a[mi][3]);
#pragma unroll
            for (int g = 0; g < 4; g++)
                ldsm_x4(sBt + swz_off(colB + g * 16 + rl, ch),
                        bb[g][0], bb[g][1], bb[g][2], bb[g][3]);
#pragma unroll
            for (int mi = 0; mi < 2; mi++)
#pragma unroll
                for (int ng = 0; ng < 8; ng++)
                    mma_s8(acc[mi][ng], a[mi],
                           bb[ng >> 1][ng & 1], bb[ng >> 1][(ng & 1) + 2]);
        }

        if (!dt && !pt) {
            // fast path: packed f16x2 exp + packed accumulation
            unsigned rowacc[4] = {0u, 0u, 0u, 0u};
            unsigned colacc[8] = {0u, 0u, 0u, 0u, 0u, 0u, 0u, 0u};
#pragma unroll
            for (int mi = 0; mi < 2; mi++)
#pragma unroll
                for (int ng = 0; ng < 8; ng++)
#pragma unroll
                    for (int qh = 0; qh < 2; qh++) {
                        float f0 = fmaf(__int_as_float(acc[mi][ng][2 * qh] + MAGIC_I), K, C0);
                        float f1 = fmaf(__int_as_float(acc[mi][ng][2 * qh + 1] + MAGIC_I), K, C0);
                        unsigned e = ex2_h2(pack_h2(f1, f0));  // lo=col c, hi=c+1
                        rowacc[mi * 2 + qh] = hadd2u(rowacc[mi * 2 + qh], e);
                        colacc[ng] = hadd2u(colacc[ng], e);
                    }
            // row partial flush (both halves are the same row)
#pragma unroll
            for (int idx = 0; idx < 4; idx++) {
                float2 fr = h2_to_f2(rowacc[idx]);
                rs[idx] += fr.x + fr.y;
            }
            // column reduce down rows (lanes 4/8/16) in f16x2
#pragma unroll
            for (int ng = 0; ng < 8; ng++) {
                unsigned c = colacc[ng];
                c = hadd2u(c, __shfl_xor_sync(0xffffffffu, c, 4));
                c = hadd2u(c, __shfl_xor_sync(0xffffffffu, c, 8));
                c = hadd2u(c, __shfl_xor_sync(0xffffffffu, c, 16));
                if (lane < 4) {
                    float2 fc = h2_to_f2(c);
                    csum[w >> 1][colB + ng * 8 + lane * 2] = fc.x;
                    csum[w >> 1][colB + ng * 8 + lane * 2 + 1] = fc.y;
                }
            }
        } else {
            // exact f32 path for diagonal / positive tiles
#pragma unroll
            for (int mi = 0; mi < 2; mi++)
#pragma unroll
                for (int ng = 0; ng < 8; ng++)
#pragma unroll
                    for (int q = 0; q < 4; q++) {
                        const int lr = rowA + mi * 16 + (q >> 1) * 8 + (lane >> 2);
                        const int lc = colB + ng * 8 + ((lane & 3) << 1) + (q & 1);
                        float f = __int_as_float(acc[mi][ng][q] + MAGIC_I);
                        const float dv = fmaf(f, K, C0);
                        if (pt && lr == lc) {
                            atomicAdd(&apos[lr], dv);
                            atomicAdd(&rowpos_b[j * 128 + lr], dv);
                        }
                        acc[mi][ng][q] = __float_as_int(
                            (dt && lr == lc) ? 0.f : ex2f(dv));
                    }
#pragma unroll
            for (int idx = 0; idx < 4; idx++) {
                const int mi = idx >> 1, qh = idx & 1;
                float r = 0.f;
#pragma unroll
                for (int ng = 0; ng < 8; ng++)
                    r += __int_as_float(acc[mi][ng][2 * qh])
                       + __int_as_float(acc[mi][ng][2 * qh + 1]);
                rs[idx] += r;
            }
#pragma unroll
            for (int ng = 0; ng < 8; ng++)
#pragma unroll
                for (int ql = 0; ql < 2; ql++) {
                    float cs = __int_as_float(acc[0][ng][ql])
                             + __int_as_float(acc[0][ng][ql + 2])
                             + __int_as_float(acc[1][ng][ql])
                             + __int_as_float(acc[1][ng][ql + 2]);
                    cs += __shfl_xor_sync(0xffffffffu, cs, 4);
                    cs += __shfl_xor_sync(0xffffffffu, cs, 8);
                    cs += __shfl_xor_sync(0xffffffffu, cs, 16);
                    if (lane < 4)
                        csum[w >> 1][colB + ng * 8 + lane * 2 + ql] = cs;
                }
        }
        __syncthreads();

        if (t + 3 < nt)
            load_tile(sB[bufi], zb + (size_t)(((ti + k0 + t + 3) & 31)) * TILEB, tid);
        CP_COMMIT();

        if (!dt && tid < 128) {
            float cs = (csum[0][tid] + csum[1][tid])
                     + (csum[2][tid] + csum[3][tid]);
            atomicAdd(&rowsum_b[j * 128 + tid], cs);
        }
        bufi = (bufi == 2) ? 0 : bufi + 1;
    }

    // CTA-end: quad-reduce row partials, combine, push rows of tile ti
#pragma unroll
    for (int idx = 0; idx < 4; idx++) {
        rs[idx] += __shfl_xor_sync(0xffffffffu, rs[idx], 1);
        rs[idx] += __shfl_xor_sync(0xffffffffu, rs[idx], 2);
    }
    if ((lane & 3) == 0) {
#pragma unroll
        for (int idx = 0; idx < 4; idx++)
            atomicAdd(&asum[rowA + (idx >> 1) * 16 + (idx & 1) * 8 + (lane >> 2)],
                      rs[idx]);
    }
    __syncthreads();
    if (tid < 128) {
        atomicAdd(&rowsum_b[ti * 128 + tid], asum[tid]);
        if (has16) atomicAdd(&rowpos_b[ti * 128 + tid], apos[tid]);
    }
}

// -------------------------------------------------------------------- finalize
__global__ void finalize_kernel(float* __restrict__ out) {
    const int r = blockIdx.x * 1024 + threadIdx.x;
    float v = 0.6931471805599453f * (lg2f(g_rowsum[r]) - g_rowpos[r]);
#pragma unroll
    for (int o = 16; o > 0; o >>= 1) v += __shfl_xor_sync(0xffffffffu, v, o);
    __shared__ float red[32];
    const int w = threadIdx.x >> 5;
    if ((threadIdx.x & 31) == 0) red[w] = v;
    __syncthreads();
    if (threadIdx.x < 32) {
        float s = red[threadIdx.x];
#pragma unroll
        for (int o = 16; o > 0; o >>= 1) s += __shfl_xor_sync(0xffffffffu, s, o);
        if (threadIdx.x == 0)
            atomicAdd(out, s * (1.f / ((float)B_ * (float)N_)));
    }
}

// ----------------------------------------------------------------- entry point
extern "C" void kernel_launch(void* const* d_in, const int* in_sizes, int n_in,
                              void* d_out, int out_size) {
    const float* Zi = (const float*)d_in[0];
    const float* Zj = (const float*)d_in[1];
    float* out = (float*)d_out;
    (void)in_sizes; (void)n_in;

    cudaFuncSetAttribute(simclr_chunk_kernel,
                         cudaFuncAttributeMaxDynamicSharedMemorySize, 65536);

    normalize_kernel<<<dim3(M_ / 32, 2, B_), 256>>>(Zi, Zj, out, out_size);
    simclr_chunk_kernel<<<dim3(CHUNKS, B_), 256, 65536>>>();
    finalize_kernel<<<B_ * N_ / 1024, 1024>>>(out);
}